// round 9
// baseline (speedup 1.0000x reference)
#include <cuda_runtime.h>
#include <math.h>
#include <stdint.h>

#define HH 512
#define WW 512
#define BN 32
#define CN 3
#define HW (HH * WW)

// Scratch (allocation-free rule: __device__ globals)
__device__ float g_Minv[BN * 9];
__device__ float g_A[HW];          // L * 0.85
__device__ float g_Z[CN * HW];     // min(z1,z2) * 0.15

// ---------------------------------------------------------------------------
// Closed-form homography (Heckbert square->quad) + 3x3 inverse, fp64.
// ---------------------------------------------------------------------------
__device__ __forceinline__ void solve_one(int b, const float* __restrict__ dst_off) {
    const double bu[4] = {0.0, 512.0, 512.0, 0.0};
    const double bv[4] = {0.0, 0.0, 512.0, 512.0};
    double u[4], v[4];
    #pragma unroll
    for (int i = 0; i < 4; i++) {
        u[i] = bu[i] + (double)dst_off[(b * 4 + i) * 2 + 0];
        v[i] = bv[i] + (double)dst_off[(b * 4 + i) * 2 + 1];
    }
    double sx  = u[0] - u[1] + u[2] - u[3];
    double sy  = v[0] - v[1] + v[2] - v[3];
    double dx1 = u[1] - u[2], dx2 = u[3] - u[2];
    double dy1 = v[1] - v[2], dy2 = v[3] - v[2];
    double den = dx1 * dy2 - dx2 * dy1;
    double g = (sx * dy2 - dx2 * sy) / den;
    double h = (dx1 * sy - sx * dy1) / den;
    double a = u[1] - u[0] + g * u[1];
    double bb = u[3] - u[0] + h * u[3];
    double c = u[0];
    double d = v[1] - v[0] + g * v[1];
    double e = v[3] - v[0] + h * v[3];
    double f = v[0];
    const double is = 1.0 / 511.0;
    double m[9] = {a * is, bb * is, c,
                   d * is, e  * is, f,
                   g * is, h  * is, 1.0};

    double det = m[0] * (m[4] * m[8] - m[5] * m[7])
               - m[1] * (m[3] * m[8] - m[5] * m[6])
               + m[2] * (m[3] * m[7] - m[4] * m[6]);
    double id = 1.0 / det;

    float* o = g_Minv + b * 9;
    o[0] = (float)( (m[4] * m[8] - m[5] * m[7]) * id);
    o[1] = (float)(-(m[1] * m[8] - m[2] * m[7]) * id);
    o[2] = (float)( (m[1] * m[5] - m[2] * m[4]) * id);
    o[3] = (float)(-(m[3] * m[8] - m[5] * m[6]) * id);
    o[4] = (float)( (m[0] * m[8] - m[2] * m[6]) * id);
    o[5] = (float)(-(m[0] * m[5] - m[2] * m[3]) * id);
    o[6] = (float)( (m[3] * m[7] - m[4] * m[6]) * id);
    o[7] = (float)(-(m[0] * m[7] - m[1] * m[6]) * id);
    o[8] = (float)( (m[0] * m[4] - m[1] * m[3]) * id);
}

// ---------------------------------------------------------------------------
// Fused setup: light mask (x0.85) + moire (x0.15) + per-batch homographies.
// ---------------------------------------------------------------------------
__global__ void setup_kernel(const float* __restrict__ dst_off,
                             const float* __restrict__ ab,
                             const float* __restrict__ centers,
                             const int* __restrict__ cflag,
                             const int* __restrict__ direction,
                             const int* __restrict__ light_xy,
                             const int* __restrict__ theta) {
    if (blockIdx.x == gridDim.x - 1) {
        int b = threadIdx.x;
        if (b < BN) solve_one(b, dst_off);
        return;
    }
    int idx = blockIdx.x * blockDim.x + threadIdx.x;
    int i = idx / WW;   // row
    int j = idx % WW;   // col

    float a = ab[0], bb = ab[1];
    float L;
    if (cflag[0] == 0) {
        int k = direction[0] - 1;  // rot90 count {0,1,2,3}
        int t = (k == 0) ? i : (k == 1) ? j : (k == 2) ? (HH - 1 - i) : (WW - 1 - j);
        L = -((bb - a) / (float)(HH - 1)) * ((float)t - (float)WW) + a;
    } else {
        float x = (float)light_xy[0], y = (float)light_xy[1];
        float d0 = sqrtf(x * x + y * y);
        float d1 = sqrtf((x - 255.f) * (x - 255.f) + y * y);
        float d2 = sqrtf(x * x + (y - 255.f) * (y - 255.f));
        float d3 = sqrtf((x - 512.f) * (x - 512.f) + (y - 512.f) * (y - 512.f));
        float ml = fmaxf(fmaxf(d0, d1), fmaxf(d2, d3));
        float dx = (float)i - x, dy = (float)j - y;
        float dist = sqrtf(dx * dx + dy * dy);
        L = dist / ml * (a - bb) + bb;
    }
    g_A[idx] = L * 0.85f;

    const float TWO_PI = 6.283185307179586f;
    float xg = (float)(i + 1), yg = (float)(j + 1);
    #pragma unroll
    for (int k = 0; k < 3; k++) {
        float cx = centers[k * 2 + 0], cy = centers[k * 2 + 1];
        float th = (float)theta[k] * 0.017453292519943295f;
        float cth = __cosf(th), sth = __sinf(th);
        float dx = xg - cx, dy = yg - cy;
        float dist = sqrtf(dx * dx + dy * dy);
        float f1 = dist - floorf(dist);               // period-1 reduction
        float t2 = cth * xg + sth * yg;
        float f2 = t2 - floorf(t2);
        float z1 = 0.5f + 0.5f * __cosf(TWO_PI * f1);
        float z2 = 0.5f + 0.5f * __cosf(TWO_PI * f2);
        g_Z[k * HW + idx] = fminf(z1, z2) * 0.15f;
    }
}

// ---------------------------------------------------------------------------
// Fused warp + blend. Block = 128 threads = one (b, y) row.
// Gather-tap sharing: the warp is near-identity in x (xs step ~ 1.001/lane),
// so lane t+1's left taps are lane t's right taps. Load only v00/v10 per
// channel; obtain v01/v11 via __shfl_down when i00_{t+1} == i00+1 (single
// check covers row+col match; ix==511 guards row-wrap aliasing; neighbor's
// zero-padding predicate == our p01/p11, so semantics compose exactly).
// Fallback predicated loads cover lane 31 + rare mismatch lanes (~1 wf).
// Halves dense gather wavefronts -> relieves the binding L1tex queue.
// ---------------------------------------------------------------------------
__global__ void __launch_bounds__(128) main_kernel(const float* __restrict__ img,
                                                   const float* __restrict__ noise,
                                                   float* __restrict__ out) {
    __shared__ float sres[3][WW];

    int b = blockIdx.z;
    int y = blockIdx.y;
    int tid = threadIdx.x;
    int lane = tid & 31;

    // ---- phase 1: gather (x = p*128 + tid) ----
    const float* Mi = g_Minv + b * 9;
    float m00 = Mi[0], m01 = Mi[1], m02 = Mi[2];
    float m10 = Mi[3], m11 = Mi[4], m12 = Mi[5];
    float m20 = Mi[6], m21 = Mi[7], m22 = Mi[8];
    float fy = (float)y;
    float ftid = (float)tid;
    float nx = m00 * ftid + (m01 * fy + m02);
    float ny = m10 * ftid + (m11 * fy + m12);
    float nd = m20 * ftid + (m21 * fy + m22);
    const float sxs = m00 * 128.f, sys = m10 * 128.f, sds = m20 * 128.f;
    const float* base = img + (size_t)b * (3 * HW);

    #pragma unroll
    for (int p = 0; p < 4; p++) {
        int x = p * 128 + tid;
        float inv = 1.0f / nd;
        float xs = nx * inv;
        float ys = ny * inv;
        nx += sxs; ny += sys; nd += sds;

        float xf = floorf(xs), yf = floorf(ys);
        float wx = xs - xf, wy = ys - yf;
        int ix = (int)xf, iy = (int)yf;
        bool vx0 = ((unsigned)ix < WW);
        bool vx1 = ((unsigned)(ix + 1) < WW);
        bool vy0 = ((unsigned)iy < HH);
        bool vy1 = ((unsigned)(iy + 1) < HH);
        bool p00 = vx0 && vy0, p01 = vx1 && vy0;
        bool p10 = vx0 && vy1, p11 = vx1 && vy1;
        float w00 = (1.f - wx) * (1.f - wy);
        float w01 = wx * (1.f - wy);
        float w10 = (1.f - wx) * wy;
        float w11 = wx * wy;
        int i00 = iy * WW + ix;   // raw; dereferenced only when predicate true

        // neighbor-match test (one integer shuffle covers row+col adjacency)
        int i00n = __shfl_down_sync(0xffffffffu, i00, 1);
        bool match = (lane < 31) && (i00n == i00 + 1) && (ix != WW - 1);

        #pragma unroll
        for (int ch = 0; ch < 3; ch++) {
            const float* pp = base + ch * HW + i00;
            float v00 = p00 ? __ldg(pp)      : 0.f;
            float v10 = p10 ? __ldg(pp + WW) : 0.f;
            float n00 = __shfl_down_sync(0xffffffffu, v00, 1);
            float n10 = __shfl_down_sync(0xffffffffu, v10, 1);
            float v01, v11;
            if (match) {
                v01 = n00;           // neighbor's predicate == our p01
                v11 = n10;
            } else {
                v01 = p01 ? __ldg(pp + 1)      : 0.f;   // lane31 + rare lanes
                v11 = p11 ? __ldg(pp + WW + 1) : 0.f;
            }
            sres[ch][x] = v00 * w00 + v01 * w01 + v10 * w10 + v11 * w11;
        }
    }

    __syncthreads();

    // ---- phase 2: vectorized blend (x0 = 4*tid) ----
    const float kn = 0.031622776601683794f;  // sqrt(0.001)
    int x0 = tid * 4;
    float4 av = *(const float4*)(g_A + (size_t)y * WW + x0);

    #pragma unroll
    for (int ch = 0; ch < 3; ch++) {
        size_t off = ((size_t)(b * 3 + ch) * HH + y) * WW + x0;
        float4 nv = __ldcs((const float4*)(noise + off));
        float4 zv = *(const float4*)(g_Z + ((size_t)ch * HH + y) * WW + x0);
        float4 rv = *(const float4*)(&sres[ch][x0]);
        float4 ov;
        ov.x = rv.x * av.x + zv.x + kn * nv.x;
        ov.y = rv.y * av.y + zv.y + kn * nv.y;
        ov.z = rv.z * av.z + zv.z + kn * nv.z;
        ov.w = rv.w * av.w + zv.w + kn * nv.w;
        __stcs((float4*)(out + off), ov);
    }
}

// ---------------------------------------------------------------------------
extern "C" void kernel_launch(void* const* d_in, const int* in_sizes, int n_in,
                              void* d_out, int out_size) {
    const float* image    = (const float*)d_in[0];
    const float* dst_off  = (const float*)d_in[1];
    const float* ab       = (const float*)d_in[2];
    const float* centers  = (const float*)d_in[3];
    const float* noise    = (const float*)d_in[4];
    const int*   c        = (const int*)d_in[5];
    const int*   direction= (const int*)d_in[6];
    const int*   light_xy = (const int*)d_in[7];
    const int*   theta    = (const int*)d_in[8];
    float* out = (float*)d_out;

    setup_kernel<<<HW / 256 + 1, 256>>>(dst_off, ab, centers, c,
                                        direction, light_xy, theta);
    dim3 grid(1, HH, BN);
    main_kernel<<<grid, 128>>>(image, noise, out);
}

// round 10
// speedup vs baseline: 1.1423x; 1.1423x over previous
#include <cuda_runtime.h>
#include <math.h>
#include <stdint.h>

#define HH 512
#define WW 512
#define BN 32
#define CN 3
#define HW (HH * WW)

// Scratch (allocation-free rule: __device__ globals)
__device__ float g_A[HW];          // L * 0.85
__device__ float g_Z[CN * HW];     // min(z1,z2) * 0.15

// ---------------------------------------------------------------------------
// Per-block fp32 closed-form homography + inverse. Cancellation-free: all
// corner differences are formed from the +/-2 jitters directly (the 0/512
// bases cancel symbolically), so fp32 keeps ~1e-7 relative accuracy.
// ---------------------------------------------------------------------------
__device__ __forceinline__ void solve_inline(int b, const float* __restrict__ dst_off,
                                             float M[9]) {
    float j0 = __ldg(dst_off + (b * 4 + 0) * 2 + 0), k0 = __ldg(dst_off + (b * 4 + 0) * 2 + 1);
    float j1 = __ldg(dst_off + (b * 4 + 1) * 2 + 0), k1 = __ldg(dst_off + (b * 4 + 1) * 2 + 1);
    float j2 = __ldg(dst_off + (b * 4 + 2) * 2 + 0), k2 = __ldg(dst_off + (b * 4 + 2) * 2 + 1);
    float j3 = __ldg(dst_off + (b * 4 + 3) * 2 + 0), k3 = __ldg(dst_off + (b * 4 + 3) * 2 + 1);

    // corners: u = (j0, 512+j1, 512+j2, j3), v = (k0, k1, 512+k2, 512+k3)
    float sx  = j0 - j1 + j2 - j3;               // bases cancel exactly
    float sy  = k0 - k1 + k2 - k3;
    float dx1 = (j1 - j2);                        // u1-u2
    float dx2 = -512.f + (j3 - j2);               // u3-u2
    float dy1 = -512.f + (k1 - k2);               // v1-v2
    float dy2 = (k3 - k2);                        // v3-v2
    float iden = 1.0f / (dx1 * dy2 - dx2 * dy1);
    float g = (sx * dy2 - dx2 * sy) * iden;
    float h = (dx1 * sy - sx * dy1) * iden;

    float u1 = 512.f + j1, u3 = j3;
    float v1 = k1, v3 = 512.f + k3;
    float a  = (512.f + (j1 - j0)) + g * u1;      // u1-u0+g*u1
    float bb = (j3 - j0) + h * u3;                // u3-u0+h*u3
    float c  = j0;
    float d  = (k1 - k0) + g * v1;                // v1-v0+g*v1
    float e  = (512.f + (k3 - k0)) + h * v3;      // v3-v0+h*v3
    float f  = k0;

    const float is = 1.0f / 511.0f;
    float m0 = a * is,  m1 = bb * is, m2 = c;
    float m3 = d * is,  m4 = e * is,  m5 = f;
    float m6 = g * is,  m7 = h * is,  m8 = 1.0f;

    float c00 =  (m4 * m8 - m5 * m7);
    float c01 = -(m3 * m8 - m5 * m6);
    float c02 =  (m3 * m7 - m4 * m6);
    float idet = 1.0f / (m0 * c00 + m1 * c01 + m2 * c02);

    M[0] = c00 * idet;
    M[1] = -(m1 * m8 - m2 * m7) * idet;
    M[2] =  (m1 * m5 - m2 * m4) * idet;
    M[3] = c01 * idet;
    M[4] =  (m0 * m8 - m2 * m6) * idet;
    M[5] = -(m0 * m5 - m2 * m3) * idet;
    M[6] = c02 * idet;
    M[7] = -(m0 * m7 - m1 * m6) * idet;
    M[8] =  (m0 * m4 - m1 * m3) * idet;
}

// ---------------------------------------------------------------------------
// Setup: light mask (x0.85) + moire (x0.15). Triggers PDL immediately so the
// main kernel's gather phase runs concurrently.
// ---------------------------------------------------------------------------
__global__ void setup_kernel(const float* __restrict__ ab,
                             const float* __restrict__ centers,
                             const int* __restrict__ cflag,
                             const int* __restrict__ direction,
                             const int* __restrict__ light_xy,
                             const int* __restrict__ theta) {
    cudaTriggerProgrammaticLaunchCompletion();   // let main launch now

    int idx = blockIdx.x * blockDim.x + threadIdx.x;
    int i = idx / WW;   // row
    int j = idx % WW;   // col

    float a = ab[0], bb = ab[1];
    float L;
    if (cflag[0] == 0) {
        int k = direction[0] - 1;  // rot90 count {0,1,2,3}
        int t = (k == 0) ? i : (k == 1) ? j : (k == 2) ? (HH - 1 - i) : (WW - 1 - j);
        L = -((bb - a) / (float)(HH - 1)) * ((float)t - (float)WW) + a;
    } else {
        float x = (float)light_xy[0], y = (float)light_xy[1];
        float d0 = sqrtf(x * x + y * y);
        float d1 = sqrtf((x - 255.f) * (x - 255.f) + y * y);
        float d2 = sqrtf(x * x + (y - 255.f) * (y - 255.f));
        float d3 = sqrtf((x - 512.f) * (x - 512.f) + (y - 512.f) * (y - 512.f));
        float ml = fmaxf(fmaxf(d0, d1), fmaxf(d2, d3));
        float dx = (float)i - x, dy = (float)j - y;
        float dist = sqrtf(dx * dx + dy * dy);
        L = dist / ml * (a - bb) + bb;
    }
    g_A[idx] = L * 0.85f;

    const float TWO_PI = 6.283185307179586f;
    float xg = (float)(i + 1), yg = (float)(j + 1);
    #pragma unroll
    for (int k = 0; k < 3; k++) {
        float cx = centers[k * 2 + 0], cy = centers[k * 2 + 1];
        float th = (float)theta[k] * 0.017453292519943295f;
        float cth = __cosf(th), sth = __sinf(th);
        float dx = xg - cx, dy = yg - cy;
        float dist = sqrtf(dx * dx + dy * dy);
        float f1 = dist - floorf(dist);               // period-1 reduction
        float t2 = cth * xg + sth * yg;
        float f2 = t2 - floorf(t2);
        float z1 = 0.5f + 0.5f * __cosf(TWO_PI * f1);
        float z2 = 0.5f + 0.5f * __cosf(TWO_PI * f2);
        g_Z[k * HW + idx] = fminf(z1, z2) * 0.15f;
    }
}

// ---------------------------------------------------------------------------
// Fused warp + blend (R4 structure). Block = 128 threads = one (b, y) row.
// Phase 1 (inline solve + gather + noise prefetch) has NO dependency on the
// setup kernel; cudaGridDependencySynchronize() gates only phase 2's
// g_A/g_Z reads.
// ---------------------------------------------------------------------------
__global__ void __launch_bounds__(128) main_kernel(const float* __restrict__ img,
                                                   const float* __restrict__ noise,
                                                   const float* __restrict__ dst_off,
                                                   float* __restrict__ out) {
    __shared__ float sres[3][WW];

    int b = blockIdx.z;
    int y = blockIdx.y;
    int tid = threadIdx.x;

    // ---- inline fp32 homography (all threads redundantly; uniform) ----
    float M[9];
    solve_inline(b, dst_off, M);

    float fy = (float)y;
    float ftid = (float)tid;
    float nx = M[0] * ftid + (M[1] * fy + M[2]);
    float ny = M[3] * ftid + (M[4] * fy + M[5]);
    float nd = M[6] * ftid + (M[7] * fy + M[8]);
    const float sxs = M[0] * 128.f, sys = M[3] * 128.f, sds = M[6] * 128.f;
    const float* base = img + (size_t)b * (3 * HW);

    #pragma unroll
    for (int p = 0; p < 4; p++) {
        int x = p * 128 + tid;
        float inv = 1.0f / nd;
        float xs = nx * inv;
        float ys = ny * inv;
        nx += sxs; ny += sys; nd += sds;

        float xf = floorf(xs), yf = floorf(ys);
        float wx = xs - xf, wy = ys - yf;
        int ix = (int)xf, iy = (int)yf;
        bool vx0 = ((unsigned)ix < WW);
        bool vx1 = ((unsigned)(ix + 1) < WW);
        bool vy0 = ((unsigned)iy < HH);
        bool vy1 = ((unsigned)(iy + 1) < HH);
        bool p00 = vx0 && vy0, p01 = vx1 && vy0;
        bool p10 = vx0 && vy1, p11 = vx1 && vy1;
        float w00 = (1.f - wx) * (1.f - wy);
        float w01 = wx * (1.f - wy);
        float w10 = (1.f - wx) * wy;
        float w11 = wx * wy;
        int i00 = iy * WW + ix;   // raw; dereferenced only when predicate true

        #pragma unroll
        for (int ch = 0; ch < 3; ch++) {
            const float* pp = base + ch * HW + i00;
            float v00 = p00 ? __ldg(pp)          : 0.f;
            float v01 = p01 ? __ldg(pp + 1)      : 0.f;
            float v10 = p10 ? __ldg(pp + WW)     : 0.f;
            float v11 = p11 ? __ldg(pp + WW + 1) : 0.f;
            sres[ch][x] = v00 * w00 + v01 * w01 + v10 * w10 + v11 * w11;
        }
    }

    __syncthreads();

    // noise is a kernel input (independent of setup) — start these loads
    // before waiting on the setup grid.
    int x0 = tid * 4;
    size_t o0 = ((size_t)(b * 3 + 0) * HH + y) * WW + x0;
    size_t o1 = ((size_t)(b * 3 + 1) * HH + y) * WW + x0;
    size_t o2 = ((size_t)(b * 3 + 2) * HH + y) * WW + x0;
    float4 nv0 = __ldcs((const float4*)(noise + o0));
    float4 nv1 = __ldcs((const float4*)(noise + o1));
    float4 nv2 = __ldcs((const float4*)(noise + o2));

    cudaGridDependencySynchronize();   // setup results (g_A, g_Z) now visible

    // ---- phase 2: vectorized blend ----
    const float kn = 0.031622776601683794f;  // sqrt(0.001)
    float4 av = *(const float4*)(g_A + (size_t)y * WW + x0);

    {
        float4 zv = *(const float4*)(g_Z + ((size_t)0 * HH + y) * WW + x0);
        float4 rv = *(const float4*)(&sres[0][x0]);
        float4 ov;
        ov.x = rv.x * av.x + zv.x + kn * nv0.x;
        ov.y = rv.y * av.y + zv.y + kn * nv0.y;
        ov.z = rv.z * av.z + zv.z + kn * nv0.z;
        ov.w = rv.w * av.w + zv.w + kn * nv0.w;
        __stcs((float4*)(out + o0), ov);
    }
    {
        float4 zv = *(const float4*)(g_Z + ((size_t)1 * HH + y) * WW + x0);
        float4 rv = *(const float4*)(&sres[1][x0]);
        float4 ov;
        ov.x = rv.x * av.x + zv.x + kn * nv1.x;
        ov.y = rv.y * av.y + zv.y + kn * nv1.y;
        ov.z = rv.z * av.z + zv.z + kn * nv1.z;
        ov.w = rv.w * av.w + zv.w + kn * nv1.w;
        __stcs((float4*)(out + o1), ov);
    }
    {
        float4 zv = *(const float4*)(g_Z + ((size_t)2 * HH + y) * WW + x0);
        float4 rv = *(const float4*)(&sres[2][x0]);
        float4 ov;
        ov.x = rv.x * av.x + zv.x + kn * nv2.x;
        ov.y = rv.y * av.y + zv.y + kn * nv2.y;
        ov.z = rv.z * av.z + zv.z + kn * nv2.z;
        ov.w = rv.w * av.w + zv.w + kn * nv2.w;
        __stcs((float4*)(out + o2), ov);
    }
}

// ---------------------------------------------------------------------------
extern "C" void kernel_launch(void* const* d_in, const int* in_sizes, int n_in,
                              void* d_out, int out_size) {
    const float* image    = (const float*)d_in[0];
    const float* dst_off  = (const float*)d_in[1];
    const float* ab       = (const float*)d_in[2];
    const float* centers  = (const float*)d_in[3];
    const float* noise    = (const float*)d_in[4];
    const int*   c        = (const int*)d_in[5];
    const int*   direction= (const int*)d_in[6];
    const int*   light_xy = (const int*)d_in[7];
    const int*   theta    = (const int*)d_in[8];
    float* out = (float*)d_out;

    setup_kernel<<<HW / 256, 256>>>(ab, centers, c, direction, light_xy, theta);

    // Launch main with programmatic dependent launch: it starts as soon as
    // setup's blocks have triggered, overlapping the gather phase with setup.
    cudaLaunchConfig_t cfg = {};
    cfg.gridDim = dim3(1, HH, BN);
    cfg.blockDim = dim3(128, 1, 1);
    cfg.dynamicSmemBytes = 0;
    cfg.stream = 0;
    cudaLaunchAttribute attr[1];
    attr[0].id = cudaLaunchAttributeProgrammaticStreamSerialization;
    attr[0].val.programmaticStreamSerializationAllowed = 1;
    cfg.attrs = attr;
    cfg.numAttrs = 1;
    cudaLaunchKernelEx(&cfg, main_kernel, image, noise, dst_off, out);
}